// round 8
// baseline (speedup 1.0000x reference)
#include <cuda_runtime.h>
#include <cstdint>

#define BQ    32
#define NN    512
#define MM    512
#define DFD   64
#define NDIAG 1023
#define NDPAD 1040          // padded (zero) so prefetch never clamps
#define TCH   8             // diagonals per chunk
#define NCHK  128           // chunks: d = 2 .. 1025
#define HROWS 256           // rows per CTA half
#define HTHR  128           // threads per dp CTA

#define LOG2E 1.4426950408889634f
#define LN2   0.6931471805599453f
#define BIGS  1.4426950408889634e10f   // 1e10 * log2(e): self-maintaining in fp32

// Diagonal-major scaled distances: g_D[b][(i+j)][i] = log2e * ||x_i - y_j||^2.
__device__ float g_D[(size_t)BQ * NDPAD * NN];
// Cross-CTA boundary: g_edge[b][d] = R'[d][256]; g_prog[b] = published-through counter.
__device__ float g_edge[BQ][1032];
__device__ int   g_prog[BQ];

// ---------------------------------------------------------------------------
__device__ __forceinline__ uint32_t smem_u32(const void* p) {
    return (uint32_t)__cvta_generic_to_shared(p);
}
__device__ __forceinline__ void st_release_cta(uint32_t addr, int v) {
    asm volatile("st.release.cta.shared.b32 [%0], %1;" :: "r"(addr), "r"(v) : "memory");
}
__device__ __forceinline__ int ld_acquire_cta(uint32_t addr) {
    int v;
    asm volatile("ld.acquire.cta.shared.b32 %0, [%1];" : "=r"(v) : "r"(addr) : "memory");
    return v;
}
__device__ __forceinline__ void st_release_gpu(int* p, int v) {
    asm volatile("st.release.gpu.global.b32 [%0], %1;" :: "l"(p), "r"(v) : "memory");
}
__device__ __forceinline__ int ld_acquire_gpu(const int* p) {
    int v;
    asm volatile("ld.acquire.gpu.global.b32 %0, [%1];" : "=r"(v) : "l"(p) : "memory");
    return v;
}
__device__ __forceinline__ float ldg_cg(const float* p) {   // L1-bypass load
    float v;
    asm volatile("ld.global.cg.f32 %0, [%1];" : "=f"(v) : "l"(p) : "memory");
    return v;
}
__device__ __forceinline__ float ex2(float x) {
    float r; asm("ex2.approx.f32 %0, %1;" : "=f"(r) : "f"(x)); return r;
}
__device__ __forceinline__ float lg2(float x) {
    float r; asm("lg2.approx.f32 %0, %1;" : "=f"(r) : "f"(x)); return r;
}

// ---------------------------------------------------------------------------
// Kernel 1: pairwise squared distances (Gram form), scaled by log2e,
// diagonal-major output. Also resets the cross-CTA handoff state for dp.
// ---------------------------------------------------------------------------
__global__ void dist_kernel(const float* __restrict__ X,
                            const float* __restrict__ Y) {
    __shared__ float sm[2 * 64 * 65];
    __shared__ float xx[64], yy[64];
    float* Xs = sm;
    float* Ys = sm + 64 * 65;

    const int b  = blockIdx.z;
    const int i0 = blockIdx.y * 64;
    const int j0 = blockIdx.x * 64;
    const int tid = threadIdx.x;

    // Per-launch reset of dp handoff state (dist completes before dp runs).
    if (blockIdx.x == 0 && blockIdx.y == 0 && tid == 0) {
        g_prog[b] = 1;
        g_edge[b][0] = BIGS;
        g_edge[b][1] = BIGS;
    }

    const float* Xb = X + ((size_t)b * NN + i0) * DFD;
    const float* Yb = Y + ((size_t)b * MM + j0) * DFD;

    #pragma unroll
    for (int idx = tid; idx < 64 * 64; idx += 256) {
        int r = idx >> 6, c = idx & 63;
        Xs[r * 65 + c] = Xb[r * 64 + c];
        Ys[r * 65 + c] = Yb[r * 64 + c];
    }
    __syncthreads();

    if (tid < 128) {
        const float* row = (tid < 64) ? &Xs[tid * 65] : &Ys[(tid - 64) * 65];
        float s = 0.f;
        #pragma unroll 8
        for (int k = 0; k < DFD; k++) s = fmaf(row[k], row[k], s);
        s *= LOG2E;
        if (tid < 64) xx[tid] = s; else yy[tid - 64] = s;
    }
    __syncthreads();

    const int ti = (tid >> 4) * 4;
    const int tj = (tid & 15) * 4;

    float acc[4][4];
    #pragma unroll
    for (int u = 0; u < 4; u++)
        #pragma unroll
        for (int v = 0; v < 4; v++) acc[u][v] = 0.f;

    #pragma unroll 4
    for (int k = 0; k < DFD; k++) {
        float xa[4], yb[4];
        #pragma unroll
        for (int u = 0; u < 4; u++) xa[u] = Xs[(ti + u) * 65 + k];
        #pragma unroll
        for (int v = 0; v < 4; v++) yb[v] = Ys[(tj + v) * 65 + k];
        #pragma unroll
        for (int u = 0; u < 4; u++)
            #pragma unroll
            for (int v = 0; v < 4; v++)
                acc[u][v] = fmaf(xa[u], yb[v], acc[u][v]);
    }
    __syncthreads();

    float* Dt = sm;                       // pitch 66 -> conflict-free diagonals
    #pragma unroll
    for (int u = 0; u < 4; u++)
        #pragma unroll
        for (int v = 0; v < 4; v++)
            Dt[(ti + u) * 66 + (tj + v)] =
                fmaf(-2.0f * LOG2E, acc[u][v], xx[ti + u] + yy[tj + v]);
    __syncthreads();

    const int warp = tid >> 5, lane = tid & 31;
    const size_t base = (size_t)b * NDPAD * NN;
    for (int dl = warp; dl < 127; dl += 8) {
        int lo = dl - 63; if (lo < 0) lo = 0;
        int hi = dl;      if (hi > 63) hi = 63;
        for (int ii = lo + lane; ii <= hi; ii += 32) {
            int gi = i0 + ii;
            int gj = j0 + dl - ii;
            g_D[base + (size_t)(gi + gj) * NN + gi] = Dt[ii * 66 + (dl - ii)];
        }
    }
}

// ---------------------------------------------------------------------------
// Soft-min cell, log2 domain, (p,q) presorted:
// cur = D' + m - log2(1 + 2^(m-mid) + 2^(m-top)).
// ---------------------------------------------------------------------------
__device__ __forceinline__ float cell(float p, float q, float late, float Dv) {
    const float m   = fminf(p, late);
    const float mid = fminf(q, fmaxf(p, late));
    const float top = fmaxf(q, late);
    const float s   = 1.0f + ex2(m - mid) + ex2(m - top);
    return Dv + m - lg2(s);
}

// ---------------------------------------------------------------------------
// Kernel 2: warp-pipelined wavefront, 2 CTAs per batch (256 rows each).
// 128 threads = 4 warps x 64 rows; thread t owns rows half*256 + 2t+1, +2.
// Intra-CTA: SMEM lane ring + edge history + monotonic smem counters.
// Inter-CTA (row-256 boundary): plain STG edges + release/acquire counter
// in global memory; consumer reads edges with L1-bypass loads.
// ---------------------------------------------------------------------------
__global__ void __launch_bounds__(HTHR, 1)
dp_kernel(const int* __restrict__ X_len, const int* __restrict__ Y_len,
          float* __restrict__ out) {
    __shared__ float edge[4][1032];    // edge[w][d] = R'[d][base + 64(w+1)]
    __shared__ float nb[4][32];        // per-warp lane ring of cur_hi
    __shared__ int   prog[4];

    const int cta  = blockIdx.x;
    const int b    = cta >> 1;
    const int half = cta & 1;
    const int tid  = threadIdx.x;
    const int w    = tid >> 5;
    const int lane = tid & 31;
    const int i_lo = half * HROWS + 2 * tid + 1;
    const int i_hi = i_lo + 1;

    const int xl  = X_len[b];
    const int tot = xl + Y_len[b];
    const bool wantlo = (xl == i_lo);
    const bool wanthi = (xl == i_hi);
    const bool isl0   = (lane == 0);
    const bool isl31  = (lane == 31);
    const int  nlane  = (lane == 0) ? 31 : lane - 1;
    const bool gprod  = (half == 0) && (w == 3);   // publishes global edges
    const bool gcons  = (half == 1) && (w == 0);   // consumes global edges

    if (tid < 8) edge[tid >> 1][tid & 1] = BIGS;
    if (tid < 4) prog[tid] = 1;
    nb[w][lane] = BIGS;
    __syncthreads();                    // the only CTA barrier

    const uint32_t prog_self = smem_u32(&prog[w]);
    const uint32_t prog_prev = smem_u32(&prog[(w == 0) ? 0 : w - 1]);

    const float2* Dp =
        (const float2*)(g_D + (size_t)b * NDPAD * NN) + half * (HROWS / 2) + tid;

    float2 Dc[TCH];
    #pragma unroll
    for (int k = 0; k < TCH; ++k) Dc[k] = Dp[(size_t)k * 256];

    float r1_lo = BIGS, r1_hi = BIGS;
    float p_lo = (tid == 0 && half == 0) ? 0.0f : BIGS, q_lo = BIGS;
    float p_hi = BIGS, q_hi = BIGS;
    float res = 0.0f;

    for (int c = 0; c < NCHK; ++c) {
        const int d0 = 2 + TCH * c;

        // Prefetch next chunk's D (padded slots; tail reads hit zero pad).
        float2 Dn[TCH];
        #pragma unroll
        for (int k = 0; k < TCH; ++k)
            Dn[k] = Dp[(size_t)(TCH * (c + 1) + k) * 256];

        // Acquire producer edges for this chunk.
        float e[TCH];
        const int needed = d0 + TCH - 2;
        if (w > 0) {
            while (ld_acquire_cta(prog_prev) < needed) __nanosleep(64);
            #pragma unroll
            for (int k = 0; k < TCH; ++k) e[k] = edge[w - 1][d0 - 1 + k];
        } else if (gcons) {
            while (ld_acquire_gpu(&g_prog[b]) < needed) __nanosleep(128);
            #pragma unroll
            for (int k = 0; k < TCH; ++k) e[k] = ldg_cg(&g_edge[b][d0 - 1 + k]);
        } else {
            #pragma unroll
            for (int k = 0; k < TCH; ++k) e[k] = BIGS;
        }

        float ed[TCH];   // boundary stash (lane 31 of producer warp)

        #pragma unroll
        for (int k = 0; k < TCH; ++k) {
            const int d = d0 + k;

            // Neighbor's cur_hi from the previous diagonal (read before write).
            const float nbv = nb[w][nlane];

            // cur_hi has no LDS dependency -> compute & publish first.
            const float cur_hi = cell(p_hi, q_hi, r1_hi, Dc[k].y);
            nb[w][lane] = cur_hi;
            if (isl31) edge[w][d] = cur_hi;
            ed[k] = cur_hi;

            const float tmp = isl0 ? e[k] : nbv;
            const float cur_lo = cell(p_lo, q_lo, tmp, Dc[k].x);

            if (d == tot)
                res = wantlo ? cur_lo : (wanthi ? cur_hi : res);

            p_hi = fminf(r1_lo, cur_lo);
            q_hi = fmaxf(r1_lo, cur_lo);
            p_lo = fminf(tmp, cur_lo);
            q_lo = fmaxf(tmp, cur_lo);
            r1_lo = cur_lo;
            r1_hi = cur_hi;
        }

        if (w < 3 && isl31)
            st_release_cta(prog_self, d0 + TCH - 1);   // orders edge STS
        if (gprod && isl31) {
            #pragma unroll
            for (int k = 0; k < TCH; ++k) g_edge[b][d0 + k] = ed[k];
            st_release_gpu(&g_prog[b], d0 + TCH - 1);  // orders edge STGs
        }

        #pragma unroll
        for (int k = 0; k < TCH; ++k) Dc[k] = Dn[k];
    }

    if (wantlo | wanthi) out[b] = res * LN2;
}

// ---------------------------------------------------------------------------
extern "C" void kernel_launch(void* const* d_in, const int* in_sizes, int n_in,
                              void* d_out, int out_size) {
    const float* X     = (const float*)d_in[0];
    const float* Y     = (const float*)d_in[1];
    const int*   X_len = (const int*)d_in[2];
    const int*   Y_len = (const int*)d_in[3];
    float*       out   = (float*)d_out;

    dist_kernel<<<dim3(8, 8, BQ), 256>>>(X, Y);
    dp_kernel<<<BQ * 2, HTHR>>>(X_len, Y_len, out);
}

// round 9
// speedup vs baseline: 1.6342x; 1.6342x over previous
#include <cuda_runtime.h>
#include <cstdint>

#define BQ    32
#define NN    512
#define MM    512
#define DFD   64
#define NDIAG 1023
#define NDPAD 1040          // padded (zero) so prefetch never clamps
#define TCH   8             // diagonals per chunk
#define NCHK  128           // chunks: d = 2 .. 1025
#define NWRP  16            // dp warps per CTA (512 threads)

#define LOG2E 1.4426950408889634f
#define LN2   0.6931471805599453f
#define BIGS  1.4426950408889634e10f   // 1e10 * log2(e): self-maintaining in fp32

// Diagonal-major scaled distances: g_D[b][(i+j)][i] = log2e * ||x_i - y_j||^2.
// Zero-initialized; positions outside the valid band are never written.
__device__ float g_D[(size_t)BQ * NDPAD * NN];

// ---------------------------------------------------------------------------
__device__ __forceinline__ uint32_t smem_u32(const void* p) {
    return (uint32_t)__cvta_generic_to_shared(p);
}
__device__ __forceinline__ void st_release_cta(uint32_t addr, int v) {
    asm volatile("st.release.cta.shared.b32 [%0], %1;" :: "r"(addr), "r"(v) : "memory");
}
__device__ __forceinline__ int ld_acquire_cta(uint32_t addr) {
    int v;
    asm volatile("ld.acquire.cta.shared.b32 %0, [%1];" : "=r"(v) : "r"(addr) : "memory");
    return v;
}
__device__ __forceinline__ float ex2(float x) {
    float r; asm("ex2.approx.f32 %0, %1;" : "=f"(r) : "f"(x)); return r;
}
__device__ __forceinline__ float lg2(float x) {
    float r; asm("lg2.approx.f32 %0, %1;" : "=f"(r) : "f"(x)); return r;
}

// ---------------------------------------------------------------------------
// Kernel 1: pairwise squared distances (Gram form), scaled by log2e,
// written in diagonal-major layout.
// ---------------------------------------------------------------------------
__global__ void dist_kernel(const float* __restrict__ X,
                            const float* __restrict__ Y) {
    __shared__ float sm[2 * 64 * 65];
    __shared__ float xx[64], yy[64];
    float* Xs = sm;
    float* Ys = sm + 64 * 65;

    const int b  = blockIdx.z;
    const int i0 = blockIdx.y * 64;
    const int j0 = blockIdx.x * 64;
    const int tid = threadIdx.x;

    const float* Xb = X + ((size_t)b * NN + i0) * DFD;
    const float* Yb = Y + ((size_t)b * MM + j0) * DFD;

    #pragma unroll
    for (int idx = tid; idx < 64 * 64; idx += 256) {
        int r = idx >> 6, c = idx & 63;
        Xs[r * 65 + c] = Xb[r * 64 + c];
        Ys[r * 65 + c] = Yb[r * 64 + c];
    }
    __syncthreads();

    if (tid < 128) {
        const float* row = (tid < 64) ? &Xs[tid * 65] : &Ys[(tid - 64) * 65];
        float s = 0.f;
        #pragma unroll 8
        for (int k = 0; k < DFD; k++) s = fmaf(row[k], row[k], s);
        s *= LOG2E;
        if (tid < 64) xx[tid] = s; else yy[tid - 64] = s;
    }
    __syncthreads();

    const int ti = (tid >> 4) * 4;
    const int tj = (tid & 15) * 4;

    float acc[4][4];
    #pragma unroll
    for (int u = 0; u < 4; u++)
        #pragma unroll
        for (int v = 0; v < 4; v++) acc[u][v] = 0.f;

    #pragma unroll 4
    for (int k = 0; k < DFD; k++) {
        float xa[4], yb[4];
        #pragma unroll
        for (int u = 0; u < 4; u++) xa[u] = Xs[(ti + u) * 65 + k];
        #pragma unroll
        for (int v = 0; v < 4; v++) yb[v] = Ys[(tj + v) * 65 + k];
        #pragma unroll
        for (int u = 0; u < 4; u++)
            #pragma unroll
            for (int v = 0; v < 4; v++)
                acc[u][v] = fmaf(xa[u], yb[v], acc[u][v]);
    }
    __syncthreads();

    float* Dt = sm;                       // pitch 66 -> conflict-free diagonals
    #pragma unroll
    for (int u = 0; u < 4; u++)
        #pragma unroll
        for (int v = 0; v < 4; v++)
            Dt[(ti + u) * 66 + (tj + v)] =
                fmaf(-2.0f * LOG2E, acc[u][v], xx[ti + u] + yy[tj + v]);
    __syncthreads();

    const int warp = tid >> 5, lane = tid & 31;
    const size_t base = (size_t)b * NDPAD * NN;
    for (int dl = warp; dl < 127; dl += 8) {
        int lo = dl - 63; if (lo < 0) lo = 0;
        int hi = dl;      if (hi > 63) hi = 63;
        for (int ii = lo + lane; ii <= hi; ii += 32) {
            int gi = i0 + ii;
            int gj = j0 + dl - ii;
            g_D[base + (size_t)(gi + gj) * NN + gi] = Dt[ii * 66 + (dl - ii)];
        }
    }
}

// ---------------------------------------------------------------------------
// Soft-min cell, log2 domain, (p,q) presorted, late input last:
// cur = D' + m - log2(1 + 2^(m-mid) + 2^(m-top)).
// ---------------------------------------------------------------------------
__device__ __forceinline__ float cell(float p, float q, float late, float Dv) {
    const float m   = fminf(p, late);
    const float mid = fminf(q, fmaxf(p, late));
    const float top = fmaxf(q, late);
    const float s   = 1.0f + ex2(m - mid) + ex2(m - top);
    return Dv + m - lg2(s);
}

// ---------------------------------------------------------------------------
// Kernel 2: warp-pipelined wavefront, 16 warps x 32 rows, ONE row per thread.
// Thread tid owns row i = tid+1; warp w rows 32w+1..32w+32. Intra-warp
// neighbor via SMEM lane ring; inter-warp via per-warp edge history +
// monotonic release/acquire counters (chunk = 8 diagonals). The early pair
// (a = retained previous ring read, c = own previous value) is presorted so
// only the ring value sits on the critical path.
// ---------------------------------------------------------------------------
__global__ void __launch_bounds__(32 * NWRP, 1)
dp_kernel(const int* __restrict__ X_len, const int* __restrict__ Y_len,
          float* __restrict__ out) {
    extern __shared__ float dsm[];
    float (*edge)[1032] = (float (*)[1032])dsm;                 // [NWRP][1032]
    float (*nb)[32]     = (float (*)[32])(dsm + NWRP * 1032);   // [NWRP][32]
    int*  prog          = (int*)(dsm + NWRP * 1032 + NWRP * 32);

    const int b    = blockIdx.x;
    const int tid  = threadIdx.x;
    const int w    = tid >> 5;
    const int lane = tid & 31;
    const int i    = tid + 1;          // owned row

    const int xl  = X_len[b];
    const int tot = xl + Y_len[b];
    const bool want  = (xl == i);
    const bool isl0  = (lane == 0);
    const bool isl31 = (lane == 31);
    const int  nlane = (lane == 0) ? 31 : lane - 1;

    if (tid < 2 * NWRP) edge[tid >> 1][tid & 1] = BIGS;
    if (tid < NWRP)     prog[tid] = 1;
    nb[w][lane] = BIGS;
    __syncthreads();                    // the only CTA barrier

    const uint32_t prog_self = smem_u32(&prog[w]);
    const uint32_t prog_prev = smem_u32(&prog[(w == 0) ? 0 : w - 1]);

    // D: thread reads position (i-1) = tid of each diagonal slot.
    const float* Dp = g_D + (size_t)b * NDPAD * NN + tid;

    float Dc[TCH];
    #pragma unroll
    for (int k = 0; k < TCH; ++k) Dc[k] = Dp[(size_t)k * NN];

    // Presorted early pair for d=2: a = R[0][0]-seed / BIG, c = BIG.
    float p = (tid == 0) ? 0.0f : BIGS;
    float q = BIGS;
    float res = 0.0f;

    for (int c = 0; c < NCHK; ++c) {
        const int d0 = 2 + TCH * c;

        // Prefetch next chunk's D (padded slots; tail reads hit zero pad).
        float Dn[TCH];
        #pragma unroll
        for (int k = 0; k < TCH; ++k)
            Dn[k] = Dp[(size_t)(TCH * (c + 1) + k) * NN];

        // Acquire producer edges for this chunk (monotonic counter, backoff).
        float e[TCH];
        if (w > 0) {
            const int needed = d0 + TCH - 2;
            while (ld_acquire_cta(prog_prev) < needed) __nanosleep(64);
            #pragma unroll
            for (int k = 0; k < TCH; ++k) e[k] = edge[w - 1][d0 - 1 + k];
        } else {
            #pragma unroll
            for (int k = 0; k < TCH; ++k) e[k] = BIGS;
        }

        #pragma unroll
        for (int k = 0; k < TCH; ++k) {
            const int d = d0 + k;

            // Neighbor's value from previous diagonal (ring read before write).
            const float nbv = nb[w][nlane];
            const float tmp = isl0 ? e[k] : nbv;   // b = R'[d-1][i-1]

            const float cur = cell(p, q, tmp, Dc[k]);

            nb[w][lane] = cur;
            if (isl31) edge[w][d] = cur;
            if (d == tot) res = want ? cur : res;

            // Presort next iteration's early pair (a = tmp, c = cur).
            p = fminf(tmp, cur);
            q = fmaxf(tmp, cur);
        }

        if (w < NWRP - 1 && isl31)
            st_release_cta(prog_self, d0 + TCH - 1);   // orders edge STS

        #pragma unroll
        for (int k = 0; k < TCH; ++k) Dc[k] = Dn[k];
    }

    if (want) out[b] = res * LN2;
}

// ---------------------------------------------------------------------------
extern "C" void kernel_launch(void* const* d_in, const int* in_sizes, int n_in,
                              void* d_out, int out_size) {
    const float* X     = (const float*)d_in[0];
    const float* Y     = (const float*)d_in[1];
    const int*   X_len = (const int*)d_in[2];
    const int*   Y_len = (const int*)d_in[3];
    float*       out   = (float*)d_out;

    const int smem_bytes = (NWRP * 1032 + NWRP * 32 + NWRP) * 4;
    static bool attr_set = false;
    if (!attr_set) {
        cudaFuncSetAttribute(dp_kernel,
                             cudaFuncAttributeMaxDynamicSharedMemorySize,
                             smem_bytes);
        attr_set = true;
    }

    dist_kernel<<<dim3(8, 8, BQ), 256>>>(X, Y);
    dp_kernel<<<BQ, 32 * NWRP, smem_bytes>>>(X_len, Y_len, out);
}

// round 10
// speedup vs baseline: 1.7543x; 1.0735x over previous
#include <cuda_runtime.h>
#include <cstdint>

#define BQ    32
#define NN    512
#define MM    512
#define DFD   64
#define NDIAG 1023
#define NDPAD 1040          // padded (zero) so prefetch never clamps
#define TCH   8             // diagonals per chunk
#define NCHK  128           // chunks: d = 2 .. 1025
#define TI    128           // dist tile rows (i)
#define TJ    128           // dist tile cols (j)

#define LOG2E 1.4426950408889634f
#define LN2   0.6931471805599453f
#define BIGS  1.4426950408889634e10f   // 1e10 * log2(e): self-maintaining in fp32

// Diagonal-major scaled distances: g_D[b][(i+j)][i] = log2e * ||x_i - y_j||^2.
// Zero-initialized; positions outside the valid band are never written.
__device__ float g_D[(size_t)BQ * NDPAD * NN];

// ---------------------------------------------------------------------------
__device__ __forceinline__ uint32_t smem_u32(const void* p) {
    return (uint32_t)__cvta_generic_to_shared(p);
}
__device__ __forceinline__ void st_release_cta(uint32_t addr, int v) {
    asm volatile("st.release.cta.shared.b32 [%0], %1;" :: "r"(addr), "r"(v) : "memory");
}
__device__ __forceinline__ int ld_acquire_cta(uint32_t addr) {
    int v;
    asm volatile("ld.acquire.cta.shared.b32 %0, [%1];" : "=r"(v) : "r"(addr) : "memory");
    return v;
}
__device__ __forceinline__ float ex2(float x) {
    float r; asm("ex2.approx.f32 %0, %1;" : "=f"(r) : "f"(x)); return r;
}
__device__ __forceinline__ float lg2(float x) {
    float r; asm("lg2.approx.f32 %0, %1;" : "=f"(r) : "f"(x)); return r;
}

// ---------------------------------------------------------------------------
// Kernel 1: pairwise squared distances (Gram form), scaled by log2e,
// diagonal-major output. 128x128 tile per CTA, 8x8 register tile per thread
// with 16-strided sub-tiles (conflict-free Y reads, broadcast X reads).
// ---------------------------------------------------------------------------
__global__ void dist_kernel(const float* __restrict__ X,
                            const float* __restrict__ Y) {
    extern __shared__ float sm[];      // 16640 floats: Xs|Ys, reused as Dt
    __shared__ float xx[TI], yy[TJ];
    float* Xs = sm;                    // [128][65]
    float* Ys = sm + TI * 65;          // [128][65]

    const int b  = blockIdx.z;
    const int i0 = blockIdx.y * TI;
    const int j0 = blockIdx.x * TJ;
    const int tid = threadIdx.x;

    const float4* Xb = (const float4*)(X + ((size_t)b * NN + i0) * DFD);
    const float4* Yb = (const float4*)(Y + ((size_t)b * MM + j0) * DFD);

    // Load tiles (float4 gmem, scalar smem stores, pitch 65).
    #pragma unroll
    for (int idx = tid; idx < TI * 16; idx += 256) {
        int r = idx >> 4, c4 = idx & 15;
        float4 v = Xb[r * 16 + c4];
        float* dst = &Xs[r * 65 + c4 * 4];
        dst[0] = v.x; dst[1] = v.y; dst[2] = v.z; dst[3] = v.w;
    }
    #pragma unroll
    for (int idx = tid; idx < TJ * 16; idx += 256) {
        int r = idx >> 4, c4 = idx & 15;
        float4 v = Yb[r * 16 + c4];
        float* dst = &Ys[r * 65 + c4 * 4];
        dst[0] = v.x; dst[1] = v.y; dst[2] = v.z; dst[3] = v.w;
    }
    __syncthreads();

    // Row norms, pre-scaled by log2e.
    if (tid < TI + TJ) {
        const float* row = (tid < TI) ? &Xs[tid * 65] : &Ys[(tid - TI) * 65];
        float s = 0.f;
        #pragma unroll 8
        for (int k = 0; k < DFD; k++) s = fmaf(row[k], row[k], s);
        s *= LOG2E;
        if (tid < TI) xx[tid] = s; else yy[tid - TI] = s;
    }
    __syncthreads();

    const int tx = tid & 15;           // j sub-lane
    const int ty = tid >> 4;           // i sub-lane

    float acc[8][8];
    #pragma unroll
    for (int u = 0; u < 8; u++)
        #pragma unroll
        for (int v = 0; v < 8; v++) acc[u][v] = 0.f;

    #pragma unroll 2
    for (int k = 0; k < DFD; k++) {
        float xa[8], yb[8];
        #pragma unroll
        for (int u = 0; u < 8; u++) xa[u] = Xs[(ty + 16 * u) * 65 + k];
        #pragma unroll
        for (int v = 0; v < 8; v++) yb[v] = Ys[(tx + 16 * v) * 65 + k];
        #pragma unroll
        for (int u = 0; u < 8; u++)
            #pragma unroll
            for (int v = 0; v < 8; v++)
                acc[u][v] = fmaf(xa[u], yb[v], acc[u][v]);
    }
    __syncthreads();

    // Stage tile (pitch 130 -> conflict-free diagonal reads: 129*ii + dl).
    float* Dt = sm;
    #pragma unroll
    for (int u = 0; u < 8; u++) {
        const float xv = xx[ty + 16 * u];
        #pragma unroll
        for (int v = 0; v < 8; v++)
            Dt[(ty + 16 * u) * 130 + (tx + 16 * v)] =
                fmaf(-2.0f * LOG2E, acc[u][v], xv + yy[tx + 16 * v]);
    }
    __syncthreads();

    // Coalesced diagonal-major writeback.
    const int warp = tid >> 5, lane = tid & 31;
    const size_t base = (size_t)b * NDPAD * NN;
    for (int dl = warp; dl < TI + TJ - 1; dl += 8) {
        int lo = dl - (TJ - 1); if (lo < 0) lo = 0;
        int hi = dl;            if (hi > TI - 1) hi = TI - 1;
        for (int ii = lo + lane; ii <= hi; ii += 32) {
            int gi = i0 + ii;
            int gj = j0 + dl - ii;
            g_D[base + (size_t)(gi + gj) * NN + gi] = Dt[ii * 130 + (dl - ii)];
        }
    }
}

// ---------------------------------------------------------------------------
// Soft-min cell, log2 domain, (p,q) presorted, late input last:
// cur = D' + m - log2(1 + 2^(m-mid) + 2^(m-top)).
// ---------------------------------------------------------------------------
__device__ __forceinline__ float cell(float p, float q, float late, float Dv) {
    const float m   = fminf(p, late);
    const float mid = fminf(q, fmaxf(p, late));
    const float top = fmaxf(q, late);
    const float s   = 1.0f + ex2(m - mid) + ex2(m - top);
    return Dv + m - lg2(s);
}

// ---------------------------------------------------------------------------
// Kernel 2: warp-pipelined wavefront (R7 structure). 8 warps x 64 rows;
// thread t owns rows 2t+1, 2t+2. SMEM lane ring intra-warp, edge history +
// monotonic release/acquire counters inter-warp. The output-capture compare
// is hoisted out of the hot loop (only the chunk containing `tot` runs the
// capture body).
// ---------------------------------------------------------------------------
__global__ void __launch_bounds__(256, 1)
dp_kernel(const int* __restrict__ X_len, const int* __restrict__ Y_len,
          float* __restrict__ out) {
    __shared__ float edge[8][1032];    // edge[w][d] = R'[d][64(w+1)]
    __shared__ float nb[8][32];        // per-warp lane ring of cur_hi
    __shared__ int   prog[8];

    const int b    = blockIdx.x;
    const int tid  = threadIdx.x;
    const int w    = tid >> 5;
    const int lane = tid & 31;
    const int i_lo = 2 * tid + 1;
    const int i_hi = i_lo + 1;

    const int xl  = X_len[b];
    const int tot = xl + Y_len[b];
    const bool wantlo = (xl == i_lo);
    const bool wanthi = (xl == i_hi);
    const bool isl0   = (lane == 0);
    const bool isl31  = (lane == 31);
    const int  nlane  = (lane == 0) ? 31 : lane - 1;

    if (tid < 16) edge[tid >> 1][tid & 1] = BIGS;
    if (tid < 8)  prog[tid] = 1;
    nb[w][lane] = BIGS;
    __syncthreads();                    // the only CTA barrier

    const uint32_t prog_self = smem_u32(&prog[w]);
    const uint32_t prog_prev = smem_u32(&prog[(w == 0) ? 0 : w - 1]);

    const float2* Dp = (const float2*)(g_D + (size_t)b * NDPAD * NN) + tid;

    float2 Dc[TCH];
    #pragma unroll
    for (int k = 0; k < TCH; ++k) Dc[k] = Dp[(size_t)k * 256];

    float r1_lo = BIGS, r1_hi = BIGS;
    float p_lo = (tid == 0) ? 0.0f : BIGS, q_lo = BIGS;
    float p_hi = BIGS, q_hi = BIGS;
    float res = 0.0f;

    for (int c = 0; c < NCHK; ++c) {
        const int d0 = 2 + TCH * c;

        // Prefetch next chunk's D (padded slots; tail reads hit zero pad).
        float2 Dn[TCH];
        #pragma unroll
        for (int k = 0; k < TCH; ++k)
            Dn[k] = Dp[(size_t)(TCH * (c + 1) + k) * 256];

        // Acquire producer edges for this chunk (monotonic counter, backoff).
        float e[TCH];
        if (w > 0) {
            const int needed = d0 + TCH - 2;
            while (ld_acquire_cta(prog_prev) < needed) __nanosleep(64);
            #pragma unroll
            for (int k = 0; k < TCH; ++k) e[k] = edge[w - 1][d0 - 1 + k];
        } else {
            #pragma unroll
            for (int k = 0; k < TCH; ++k) e[k] = BIGS;
        }

        if ((unsigned)(tot - d0) < TCH) {
            // ---- capture body: the one chunk that can produce the output ----
            #pragma unroll
            for (int k = 0; k < TCH; ++k) {
                const int d = d0 + k;
                const float nbv = nb[w][nlane];

                const float cur_hi = cell(p_hi, q_hi, r1_hi, Dc[k].y);
                nb[w][lane] = cur_hi;
                if (isl31) edge[w][d] = cur_hi;

                const float tmp = isl0 ? e[k] : nbv;
                const float cur_lo = cell(p_lo, q_lo, tmp, Dc[k].x);

                if (d == tot)
                    res = wantlo ? cur_lo : (wanthi ? cur_hi : res);

                p_hi = fminf(r1_lo, cur_lo);
                q_hi = fmaxf(r1_lo, cur_lo);
                p_lo = fminf(tmp, cur_lo);
                q_lo = fmaxf(tmp, cur_lo);
                r1_lo = cur_lo;
                r1_hi = cur_hi;
            }
        } else {
            // ---- hot body: no output-capture instructions ----
            #pragma unroll
            for (int k = 0; k < TCH; ++k) {
                const int d = d0 + k;
                const float nbv = nb[w][nlane];

                const float cur_hi = cell(p_hi, q_hi, r1_hi, Dc[k].y);
                nb[w][lane] = cur_hi;
                if (isl31) edge[w][d] = cur_hi;

                const float tmp = isl0 ? e[k] : nbv;
                const float cur_lo = cell(p_lo, q_lo, tmp, Dc[k].x);

                p_hi = fminf(r1_lo, cur_lo);
                q_hi = fmaxf(r1_lo, cur_lo);
                p_lo = fminf(tmp, cur_lo);
                q_lo = fmaxf(tmp, cur_lo);
                r1_lo = cur_lo;
                r1_hi = cur_hi;
            }
        }

        if (w < 7 && isl31)
            st_release_cta(prog_self, d0 + TCH - 1);   // orders edge STS

        #pragma unroll
        for (int k = 0; k < TCH; ++k) Dc[k] = Dn[k];
    }

    if (wantlo | wanthi) out[b] = res * LN2;
}

// ---------------------------------------------------------------------------
extern "C" void kernel_launch(void* const* d_in, const int* in_sizes, int n_in,
                              void* d_out, int out_size) {
    const float* X     = (const float*)d_in[0];
    const float* Y     = (const float*)d_in[1];
    const int*   X_len = (const int*)d_in[2];
    const int*   Y_len = (const int*)d_in[3];
    float*       out   = (float*)d_out;

    const int dist_smem = (TI * 65 + TJ * 65) * 4;   // 66560 B
    static bool attr_set = false;
    if (!attr_set) {
        cudaFuncSetAttribute(dist_kernel,
                             cudaFuncAttributeMaxDynamicSharedMemorySize,
                             dist_smem);
        attr_set = true;
    }

    dist_kernel<<<dim3(MM / TJ, NN / TI, BQ), 256, dist_smem>>>(X, Y);
    dp_kernel<<<BQ, 256>>>(X_len, Y_len, out);
}